// round 8
// baseline (speedup 1.0000x reference)
#include <cuda_runtime.h>

#define NBINS 15
#define BS 256
#define NACC (2 + NBINS)
#define BLOCKS_PER_SM 5
#define GRID (148 * BLOCKS_PER_SM)

// [0]=focal sum (log2 units), [1]=cp sum, [2..16]=per-bin sum of (y - p)
__device__ double g_acc[NACC];
__device__ unsigned g_count;   // zero-initialized at module load

__device__ __forceinline__ float warp_sum(float v) {
#pragma unroll
    for (int o = 16; o > 0; o >>= 1) v += __shfl_down_sync(0xffffffffu, v, o);
    return v;
}

__device__ __forceinline__ unsigned smem_u32(const void* p) {
    unsigned a;
    asm("{ .reg .u64 t; cvta.to.shared.u64 t, %1; cvt.u32.u64 %0, t; }"
        : "=r"(a) : "l"(p));
    return a;
}

// 16B async copy global->shared, zero-fill when sz==0 (L1-bypass .cg path)
__device__ __forceinline__ void cpa16(unsigned dst, const void* src, int sz) {
    asm volatile("cp.async.cg.shared.global [%0], [%1], 16, %2;"
                 :: "r"(dst), "l"(src), "r"(sz) : "memory");
}
#define CP_COMMIT() asm volatile("cp.async.commit_group;" ::: "memory")
#define CP_WAIT1()  asm volatile("cp.async.wait_group 1;" ::: "memory")
#define CP_WAIT0()  asm volatile("cp.async.wait_group 0;" ::: "memory")

__device__ __forceinline__ void process1(float p, float u, int t,
                                         float& facc, float& cacc,
                                         float* __restrict__ histcol) {
    bool pos = (t != 0);

    // focal in log2 units: acc += alpha*(1-pt)^2 * log2(pt+1e-12); *(-ln2) at finalize
    float pt = pos ? p : 1.0f - p;
    float om = 1.0f - pt;
    float om2 = om * om;
    if (!pos) om2 += om2;               // alpha fold: x2 for negatives
    facc = fmaf(om2, __log2f(pt + 1e-12f), facc);

    // confidence penalty: pos&p<tau -> u^2 ; !pos&p>tau -> (1-u)^2
    float v = pos ? u : 1.0f - u;
    bool cond = ((p < 0.7f) == pos);
    if (cond) cacc = fmaf(v, v, cacc);

    // ECE binning: bin = min((int)(p*15), 14); accumulate (y - p)
    int b = (int)fminf(p * 15.0f, 14.0f);
    float d = (pos ? 1.0f : 0.0f) - p;
    histcol[b * BS] += d;
}

__device__ __forceinline__ void process4(float4 pv, float4 uv, int4 tv,
                                         float& facc, float& cacc,
                                         float* __restrict__ col) {
    process1(pv.x, uv.x, tv.x, facc, cacc, col);
    process1(pv.y, uv.y, tv.y, facc, cacc, col);
    process1(pv.z, uv.z, tv.z, facc, cacc, col);
    process1(pv.w, uv.w, tv.w, facc, cacc, col);
}

__global__ void __launch_bounds__(BS) fcl_main(
    const float* __restrict__ p_hat, const float* __restrict__ u_hat,
    const int* __restrict__ targets, float* __restrict__ out, int n)
{
    // double-buffered per-thread staging (cp.async targets) + histogram
    __shared__ float4 sp[2][BS];
    __shared__ float4 su[2][BS];
    __shared__ int4   st[2][BS];
    __shared__ float  hist[NBINS * BS];   // hist[b*BS+tid]: conflict-free columns
    __shared__ float  red[2][BS / 32];
    __shared__ bool   is_last;

    const int tid  = threadIdx.x;
    const int lane = tid & 31;
    const int warp = tid >> 5;
    float* col = &hist[tid];

#pragma unroll
    for (int b = 0; b < NBINS; b++) hist[b * BS + tid] = 0.0f;
    __syncthreads();

    float facc = 0.0f, cacc = 0.0f;

    const int n4 = n >> 2;
    const float4* __restrict__ p4 = (const float4*)p_hat;
    const float4* __restrict__ u4 = (const float4*)u_hat;
    const int4*   __restrict__ t4 = (const int4*)targets;

    const int stride = GRID * BS;
    const int i0 = blockIdx.x * BS + tid;
    const int ITERS = (n4 + stride - 1) / stride;   // uniform across all threads

    // per-thread smem slot addresses for the two stages
    const unsigned ap0 = smem_u32(&sp[0][tid]), ap1 = smem_u32(&sp[1][tid]);
    const unsigned au0 = smem_u32(&su[0][tid]), au1 = smem_u32(&su[1][tid]);
    const unsigned at0 = smem_u32(&st[0][tid]), at1 = smem_u32(&st[1][tid]);

    // prologue: stage iters 0 and 1 (zero-fill when out of range -> contributes 0)
    {
        int ia = i0;            bool va = ia < n4; int ca = va ? ia : 0; int sa = va ? 16 : 0;
        cpa16(ap0, &p4[ca], sa); cpa16(au0, &u4[ca], sa); cpa16(at0, &t4[ca], sa);
        CP_COMMIT();
        int ib = i0 + stride;   bool vb = ib < n4; int cb = vb ? ib : 0; int sb = vb ? 16 : 0;
        cpa16(ap1, &p4[cb], sb); cpa16(au1, &u4[cb], sb); cpa16(at1, &t4[cb], sb);
        CP_COMMIT();
    }

    int inext = i0 + 2 * stride;
    for (int it = 0; it < ITERS; it++, inext += stride) {
        CP_WAIT1();                       // stage 'it' complete; 'it+1' still in flight
        int s = it & 1;
        float4 pv = sp[s][tid];
        float4 uv = su[s][tid];
        int4   tv = st[s][tid];
        // refill this stage with iter it+2 before computing (keeps 2 stages in flight)
        bool v = inext < n4; int ci = v ? inext : 0; int sz = v ? 16 : 0;
        cpa16(s ? ap1 : ap0, &p4[ci], sz);
        cpa16(s ? au1 : au0, &u4[ci], sz);
        cpa16(s ? at1 : at0, &t4[ci], sz);
        CP_COMMIT();
        process4(pv, uv, tv, facc, cacc, col);
    }
    CP_WAIT0();                           // drain stale prefetches before smem reuse/exit

    // scalar tail (n not divisible by 4)
    for (int j = (n4 << 2) + i0; j < n; j += stride) {
        process1(p_hat[j], u_hat[j], targets[j], facc, cacc, col);
    }
    __syncthreads();

    // block-reduce focal / cp
    facc = warp_sum(facc);
    cacc = warp_sum(cacc);
    if (lane == 0) { red[0][warp] = facc; red[1][warp] = cacc; }
    __syncthreads();
    if (warp == 0) {
        float f = (lane < BS / 32) ? red[0][lane] : 0.0f;
        float c = (lane < BS / 32) ? red[1][lane] : 0.0f;
        f = warp_sum(f);
        c = warp_sum(c);
        if (lane == 0) {
            atomicAdd(&g_acc[0], (double)f);
            atomicAdd(&g_acc[1], (double)c);
        }
    }

    // block-reduce each bin column, one double atomic per bin per block
    for (int b = warp; b < NBINS; b += BS / 32) {
        float s = 0.0f;
#pragma unroll
        for (int j = lane; j < BS; j += 32) s += hist[b * BS + j];
        s = warp_sum(s);
        if (lane == 0) atomicAdd(&g_acc[2 + b], (double)s);
    }

    // last-block-done: finalize + reset accumulators for next graph replay
    __threadfence();
    if (tid == 0) {
        unsigned v = atomicInc(&g_count, GRID - 1);  // wraps to 0 on last block
        is_last = (v == GRID - 1);
    }
    __syncthreads();
    if (is_last && tid == 0) {
        double invn  = 1.0 / (double)n;
        double focal = -0.6931471805599453 * g_acc[0] * invn;  // -ln2 * log2-units
        double cp    = g_acc[1] * invn;
        double e     = 0.0;
#pragma unroll
        for (int b = 0; b < NBINS; b++) e += fabs(g_acc[2 + b]);
        e *= invn;
        out[0] = (float)(focal + 6.0 * cp + 5.0 * e);
#pragma unroll
        for (int a = 0; a < NACC; a++) g_acc[a] = 0.0;
    }
}

extern "C" void kernel_launch(void* const* d_in, const int* in_sizes, int n_in,
                              void* d_out, int out_size) {
    const float* p_hat   = (const float*)d_in[0];
    const float* u_hat   = (const float*)d_in[1];
    const int*   targets = (const int*)d_in[2];
    float* out = (float*)d_out;
    int n = in_sizes[0];

    fcl_main<<<GRID, BS>>>(p_hat, u_hat, targets, out, n);
}